// round 4
// baseline (speedup 1.0000x reference)
#include <cuda_runtime.h>
#include <cuda_bf16.h>
#include <cstdint>

// Problem constants
#define BB 64
#define TT 128
#define DD 512
#define HH 30
#define TM 98
static constexpr float INV_TEMP = 1.0f / 0.07f;

// Scratch (device globals: no allocation allowed)
__device__ __align__(16) __nv_bfloat16 g_zbf[BB * TT * DD];    // bf16 z_seq
__device__ __align__(16) __nv_bfloat16 g_cbf[BB * TT * DD];    // bf16 c_seq
__device__ __align__(16) __nv_bfloat16 g_cproj[BB * TT * DD];  // bf16 c_proj
__device__ __align__(16) __nv_bfloat16 g_Wt[DD * DD];          // bf16 W^T ([n][p])
__device__ float g_partials[TM * HH];

// ---------------------------------------------------------------------------
// PTX helpers
// ---------------------------------------------------------------------------
__device__ __forceinline__ uint32_t smem_u32(const void* p) {
    return (uint32_t)__cvta_generic_to_shared(p);
}
__device__ __forceinline__ void ldm_x4(uint32_t& a0, uint32_t& a1, uint32_t& a2,
                                       uint32_t& a3, uint32_t addr) {
    asm volatile("ldmatrix.sync.aligned.m8n8.x4.shared.b16 {%0,%1,%2,%3}, [%4];\n"
                 : "=r"(a0), "=r"(a1), "=r"(a2), "=r"(a3) : "r"(addr));
}
__device__ __forceinline__ void ldm_x2(uint32_t& b0, uint32_t& b1, uint32_t addr) {
    asm volatile("ldmatrix.sync.aligned.m8n8.x2.shared.b16 {%0,%1}, [%2];\n"
                 : "=r"(b0), "=r"(b1) : "r"(addr));
}
__device__ __forceinline__ void mma_bf16(float* c, uint32_t a0, uint32_t a1,
                                         uint32_t a2, uint32_t a3,
                                         uint32_t b0, uint32_t b1) {
    asm volatile(
        "mma.sync.aligned.m16n8k16.row.col.f32.bf16.bf16.f32 "
        "{%0,%1,%2,%3}, {%4,%5,%6,%7}, {%8,%9}, {%0,%1,%2,%3};\n"
        : "+f"(c[0]), "+f"(c[1]), "+f"(c[2]), "+f"(c[3])
        : "r"(a0), "r"(a1), "r"(a2), "r"(a3), "r"(b0), "r"(b1));
}
__device__ __forceinline__ void cp_async16(uint32_t dst, const void* src) {
    asm volatile("cp.async.ca.shared.global [%0], [%1], 16;\n" :: "r"(dst), "l"(src));
}
__device__ __forceinline__ void cp_commit() {
    asm volatile("cp.async.commit_group;\n");
}
template <int N>
__device__ __forceinline__ void cp_wait() {
    asm volatile("cp.async.wait_group %0;\n" :: "n"(N));
}

// ---------------------------------------------------------------------------
// Convert fp32 -> bf16 (vectorized)
// ---------------------------------------------------------------------------
__global__ void k_convert(const float* __restrict__ src, __nv_bfloat16* __restrict__ dst) {
    int i = blockIdx.x * blockDim.x + threadIdx.x;
    int idx = i * 4;
    if (idx < BB * TT * DD) {
        float4 v = *(const float4*)(src + idx);
        *(__nv_bfloat162*)(dst + idx) = __floats2bfloat162_rn(v.x, v.y);
        *(__nv_bfloat162*)(dst + idx + 2) = __floats2bfloat162_rn(v.z, v.w);
    }
}

// Transpose+convert W fp32 [p][n] -> bf16 g_Wt [n][p]
__global__ void k_convert_w(const float* __restrict__ W) {
    int i = blockIdx.x * blockDim.x + threadIdx.x;
    if (i < DD * DD) {
        int n = i >> 9;
        int p = i & 511;
        g_Wt[i] = __float2bfloat16(W[p * DD + n]);
    }
}

// ---------------------------------------------------------------------------
// GEMM1: c_proj = c @ W + b.  M=8192, N=512, K=512.
// CTA tile 128x128, 256 thr (8 warps, warp tile 32x64), K-chunk 64, cp.async 2-stage.
// ---------------------------------------------------------------------------
#define G1_LD 72
#define G1_TILE_B (128 * G1_LD * 2)      // 18432
#define G1_STAGE_B (2 * G1_TILE_B)      // 36864
#define G1_SMEM (2 * G1_STAGE_B)        // 73728

__global__ __launch_bounds__(256) void k_gemm1(const float* __restrict__ bias) {
    extern __shared__ char sm[];
    const int tid = threadIdx.x;
    const int w = tid >> 5;
    const int lane = tid & 31;
    const int wr = w >> 1;          // 0..3 : rows wr*32
    const int wc = w & 1;           // 0..1 : cols wc*64
    const int g = lane >> 2;
    const int t4 = lane & 3;
    const int m0 = blockIdx.x * 128;
    const int n0 = blockIdx.y * 128;

    float acc[2][8][4];
#pragma unroll
    for (int a = 0; a < 2; a++)
#pragma unroll
        for (int nt = 0; nt < 8; nt++)
#pragma unroll
            for (int e = 0; e < 4; e++) acc[a][nt][e] = 0.f;

    auto issue = [&](int kc, int st) {
        char* base = sm + st * G1_STAGE_B;
        uint32_t sa = smem_u32(base);
        uint32_t sb = smem_u32(base + G1_TILE_B);
#pragma unroll
        for (int it = 0; it < 4; it++) {
            int idx = tid + it * 256;          // 0..1023
            int r = idx >> 3, cu = idx & 7;
            cp_async16(sa + (r * G1_LD + cu * 8) * 2,
                       g_cbf + (size_t)(m0 + r) * DD + kc * 64 + cu * 8);
        }
#pragma unroll
        for (int it = 0; it < 4; it++) {
            int idx = tid + it * 256;
            int r = idx >> 3, cu = idx & 7;
            cp_async16(sb + (r * G1_LD + cu * 8) * 2,
                       g_Wt + (size_t)(n0 + r) * DD + kc * 64 + cu * 8);
        }
        cp_commit();
    };

    issue(0, 0);

    for (int kc = 0; kc < 8; kc++) {
        if (kc < 7) issue(kc + 1, (kc + 1) & 1);
        if (kc < 7) cp_wait<1>(); else cp_wait<0>();
        __syncthreads();
        char* base = sm + (kc & 1) * G1_STAGE_B;
        uint32_t sa = smem_u32(base);
        uint32_t sb = smem_u32(base + G1_TILE_B);
#pragma unroll
        for (int ks = 0; ks < 4; ks++) {
            uint32_t af[2][4];
#pragma unroll
            for (int a = 0; a < 2; a++) {
                uint32_t addr = sa + ((wr * 32 + a * 16 + (lane & 15)) * G1_LD +
                                      ks * 16 + (lane >> 4) * 8) * 2;
                ldm_x4(af[a][0], af[a][1], af[a][2], af[a][3], addr);
            }
#pragma unroll
            for (int nt = 0; nt < 8; nt++) {
                uint32_t b0, b1;
                uint32_t addr = sb + ((wc * 64 + nt * 8 + (lane & 7)) * G1_LD +
                                      ks * 16 + ((lane >> 3) & 1) * 8) * 2;
                ldm_x2(b0, b1, addr);
#pragma unroll
                for (int a = 0; a < 2; a++)
                    mma_bf16(acc[a][nt], af[a][0], af[a][1], af[a][2], af[a][3], b0, b1);
            }
        }
        __syncthreads();
    }

    // Epilogue: bias + bf16 store
#pragma unroll
    for (int a = 0; a < 2; a++) {
        int r0 = m0 + wr * 32 + a * 16 + g;
#pragma unroll
        for (int nt = 0; nt < 8; nt++) {
            int col = n0 + wc * 64 + nt * 8 + t4 * 2;
            float bv0 = bias[col], bv1 = bias[col + 1];
            *(__nv_bfloat162*)(g_cproj + (size_t)r0 * DD + col) =
                __floats2bfloat162_rn(acc[a][nt][0] + bv0, acc[a][nt][1] + bv1);
            *(__nv_bfloat162*)(g_cproj + (size_t)(r0 + 8) * DD + col) =
                __floats2bfloat162_rn(acc[a][nt][2] + bv0, acc[a][nt][3] + bv1);
        }
    }
}

// ---------------------------------------------------------------------------
// Fused scores + LSE - diag.
// Grid (98, 15): CTA = (t, k-pair {2kg+1, 2kg+2}). 128 thr, 4 warps.
// Warp w: k-index w>>1, row-half w&1 (32 rows x 64 cols, 2 A-frags share B-frags).
// cp.async 2-stage over 4 D-chunks of 128. SMEM/stage: C,Z0,Z1 tiles (64x136 bf16).
// ---------------------------------------------------------------------------
#define S_LD 136
#define S_TILE_B (64 * S_LD * 2)        // 17408
#define S_STAGE_B (3 * S_TILE_B)        // 52224
#define S_SMEM (2 * S_STAGE_B + 16)     // 104464

__global__ __launch_bounds__(128) void k_scores() {
    extern __shared__ char sm[];
    float* sRed = (float*)(sm + 2 * S_STAGE_B);

    const int t = blockIdx.x;
    const int k0 = blockIdx.y * 2 + 1;
    const int s0 = t + k0;
    const int s1 = s0 + 1;
    const int tid = threadIdx.x;
    const int w = tid >> 5;
    const int lane = tid & 31;
    const int kidx = w >> 1;        // which k this warp computes
    const int rh = w & 1;           // row half: rows rh*32..+32
    const int g = lane >> 2;
    const int t4 = lane & 3;

    float acc[2][8][4];
#pragma unroll
    for (int a = 0; a < 2; a++)
#pragma unroll
        for (int nt = 0; nt < 8; nt++)
#pragma unroll
            for (int e = 0; e < 4; e++) acc[a][nt][e] = 0.f;

    auto issue = [&](int ch, int st) {
        char* base = sm + st * S_STAGE_B;
        uint32_t sc = smem_u32(base);
        uint32_t sz0 = smem_u32(base + S_TILE_B);
        uint32_t sz1 = smem_u32(base + 2 * S_TILE_B);
#pragma unroll
        for (int it = 0; it < 8; it++) {
            int idx = tid + it * 128;       // 0..1023 -> 64 rows x 16 uint4
            int r = idx >> 4, cu = idx & 15;
            uint32_t so = (r * S_LD + cu * 8) * 2;
            size_t go = (size_t)r * TT * DD + ch * 128 + cu * 8;
            cp_async16(sc + so, g_cproj + go + (size_t)t * DD);
            cp_async16(sz0 + so, g_zbf + go + (size_t)s0 * DD);
            cp_async16(sz1 + so, g_zbf + go + (size_t)s1 * DD);
        }
        cp_commit();
    };

    issue(0, 0);

    for (int ch = 0; ch < 4; ch++) {
        if (ch < 3) issue(ch + 1, (ch + 1) & 1);
        if (ch < 3) cp_wait<1>(); else cp_wait<0>();
        __syncthreads();
        char* base = sm + (ch & 1) * S_STAGE_B;
        uint32_t sc = smem_u32(base);
        uint32_t sz = smem_u32(base + (1 + kidx) * S_TILE_B);
#pragma unroll
        for (int ks = 0; ks < 8; ks++) {
            uint32_t af[2][4];
#pragma unroll
            for (int a = 0; a < 2; a++) {
                uint32_t addr = sc + ((rh * 32 + a * 16 + (lane & 15)) * S_LD +
                                      ks * 16 + (lane >> 4) * 8) * 2;
                ldm_x4(af[a][0], af[a][1], af[a][2], af[a][3], addr);
            }
#pragma unroll
            for (int nt = 0; nt < 8; nt++) {
                uint32_t b0, b1;
                uint32_t addr = sz + ((nt * 8 + (lane & 7)) * S_LD +
                                      ks * 16 + ((lane >> 3) & 1) * 8) * 2;
                ldm_x2(b0, b1, addr);
#pragma unroll
                for (int a = 0; a < 2; a++)
                    mma_bf16(acc[a][nt], af[a][0], af[a][1], af[a][2], af[a][3], b0, b1);
            }
        }
        __syncthreads();
    }

    // Epilogue: per-row logsumexp minus diagonal, accumulate per warp.
    float local = 0.f;
#pragma unroll
    for (int a = 0; a < 2; a++) {
#pragma unroll
        for (int rp = 0; rp < 2; rp++) {
            const int e0 = rp * 2;
            float m = -3.4e38f;
#pragma unroll
            for (int nt = 0; nt < 8; nt++)
                m = fmaxf(m, fmaxf(acc[a][nt][e0], acc[a][nt][e0 + 1]));
            m = fmaxf(m, __shfl_xor_sync(0xffffffffu, m, 1));
            m = fmaxf(m, __shfl_xor_sync(0xffffffffu, m, 2));
            float se = 0.f;
#pragma unroll
            for (int nt = 0; nt < 8; nt++) {
                se += expf((acc[a][nt][e0] - m) * INV_TEMP);
                se += expf((acc[a][nt][e0 + 1] - m) * INV_TEMP);
            }
            se += __shfl_xor_sync(0xffffffffu, se, 1);
            se += __shfl_xor_sync(0xffffffffu, se, 2);
            float lse = m * INV_TEMP + logf(se);
            int i = rh * 32 + a * 16 + g + rp * 8;     // global row == diag col
            if (t4 == ((i >> 1) & 3))
                local += lse - acc[a][i >> 3][e0 + (i & 1)] * INV_TEMP;
        }
    }
#pragma unroll
    for (int off = 16; off > 0; off >>= 1)
        local += __shfl_xor_sync(0xffffffffu, local, off);
    if (lane == 0) sRed[w] = local;
    __syncthreads();
    if (tid == 0) {
        g_partials[t * HH + (k0 - 1)] = sRed[0] + sRed[1];
        g_partials[t * HH + k0] = sRed[2] + sRed[3];
    }
}

// ---------------------------------------------------------------------------
// Final deterministic reduction
// ---------------------------------------------------------------------------
__global__ void k_reduce(float* __restrict__ out) {
    __shared__ float sh[256];
    int tid = threadIdx.x;
    float ssum = 0.f;
    for (int i = tid; i < TM * HH; i += 256) ssum += g_partials[i];
    sh[tid] = ssum;
    __syncthreads();
    for (int off = 128; off > 0; off >>= 1) {
        if (tid < off) sh[tid] += sh[tid + off];
        __syncthreads();
    }
    if (tid == 0) out[0] = sh[0] / (float)(TM * HH * BB);
}

// ---------------------------------------------------------------------------
extern "C" void kernel_launch(void* const* d_in, const int* in_sizes, int n_in,
                              void* d_out, int out_size) {
    const float* z = (const float*)d_in[0];
    const float* c = (const float*)d_in[1];
    const float* W = (const float*)d_in[2];
    const float* bias = (const float*)d_in[3];
    float* out = (float*)d_out;
    (void)in_sizes; (void)n_in; (void)out_size;

    static bool attr_done = false;
    if (!attr_done) {
        cudaFuncSetAttribute(k_scores, cudaFuncAttributeMaxDynamicSharedMemorySize, S_SMEM);
        cudaFuncSetAttribute(k_gemm1, cudaFuncAttributeMaxDynamicSharedMemorySize, G1_SMEM);
        attr_done = true;
    }

    __nv_bfloat16* zb = nullptr;
    __nv_bfloat16* cb = nullptr;
    cudaGetSymbolAddress((void**)&zb, g_zbf);
    cudaGetSymbolAddress((void**)&cb, g_cbf);

    k_convert<<<4096, 256>>>(z, zb);
    k_convert<<<4096, 256>>>(c, cb);
    k_convert_w<<<(DD * DD + 511) / 512, 512>>>(W);
    k_gemm1<<<dim3(64, 4), 256, G1_SMEM>>>(bias);
    k_scores<<<dim3(TM, 15), 128, S_SMEM>>>();
    k_reduce<<<1, 256>>>(out);
}

// round 5
// speedup vs baseline: 2.2876x; 2.2876x over previous
#include <cuda_runtime.h>
#include <cuda_bf16.h>
#include <cstdint>

// Problem constants
#define BB 64
#define TT 128
#define DD 512
#define HH 30
#define TM 98
static constexpr float INV_TEMP = 1.0f / 0.07f;

// Scratch (device globals: no allocation allowed)
__device__ __align__(16) __nv_bfloat16 g_zbf[BB * TT * DD];    // bf16 z_seq
__device__ __align__(16) __nv_bfloat16 g_cbf[BB * TT * DD];    // bf16 c_seq
__device__ __align__(16) __nv_bfloat16 g_cproj[BB * TT * DD];  // bf16 c_proj
__device__ __align__(16) __nv_bfloat16 g_Wt[DD * DD];          // bf16 W^T ([n][p])
__device__ float g_partials[TM * HH];

// ---------------------------------------------------------------------------
// PTX helpers
// ---------------------------------------------------------------------------
__device__ __forceinline__ uint32_t smem_u32(const void* p) {
    return (uint32_t)__cvta_generic_to_shared(p);
}
__device__ __forceinline__ void ldm_x4(uint32_t& a0, uint32_t& a1, uint32_t& a2,
                                       uint32_t& a3, uint32_t addr) {
    asm volatile("ldmatrix.sync.aligned.m8n8.x4.shared.b16 {%0,%1,%2,%3}, [%4];\n"
                 : "=r"(a0), "=r"(a1), "=r"(a2), "=r"(a3) : "r"(addr));
}
__device__ __forceinline__ void mma_bf16(float* c, uint32_t a0, uint32_t a1,
                                         uint32_t a2, uint32_t a3,
                                         uint32_t b0, uint32_t b1) {
    asm volatile(
        "mma.sync.aligned.m16n8k16.row.col.f32.bf16.bf16.f32 "
        "{%0,%1,%2,%3}, {%4,%5,%6,%7}, {%8,%9}, {%0,%1,%2,%3};\n"
        : "+f"(c[0]), "+f"(c[1]), "+f"(c[2]), "+f"(c[3])
        : "r"(a0), "r"(a1), "r"(a2), "r"(a3), "r"(b0), "r"(b1));
}
__device__ __forceinline__ void cp_async16(uint32_t dst, const void* src) {
    asm volatile("cp.async.ca.shared.global [%0], [%1], 16;\n" :: "r"(dst), "l"(src));
}
__device__ __forceinline__ void cp_commit() {
    asm volatile("cp.async.commit_group;\n");
}
template <int N>
__device__ __forceinline__ void cp_wait() {
    asm volatile("cp.async.wait_group %0;\n" :: "n"(N));
}

// ---------------------------------------------------------------------------
// Convert fp32 -> bf16 (vectorized)
// ---------------------------------------------------------------------------
__global__ void k_convert(const float* __restrict__ src, __nv_bfloat16* __restrict__ dst) {
    int i = blockIdx.x * blockDim.x + threadIdx.x;
    int idx = i * 4;
    if (idx < BB * TT * DD) {
        float4 v = *(const float4*)(src + idx);
        *(__nv_bfloat162*)(dst + idx) = __floats2bfloat162_rn(v.x, v.y);
        *(__nv_bfloat162*)(dst + idx + 2) = __floats2bfloat162_rn(v.z, v.w);
    }
}

// Transpose+convert W fp32 [p][n] -> bf16 g_Wt [n][p]
__global__ void k_convert_w(const float* __restrict__ W) {
    int i = blockIdx.x * blockDim.x + threadIdx.x;
    if (i < DD * DD) {
        int n = i >> 9;
        int p = i & 511;
        g_Wt[i] = __float2bfloat16(W[p * DD + n]);
    }
}

// ---------------------------------------------------------------------------
// GEMM1: c_proj = c @ W + b.  M=8192, N=512, K=512.
// CTA tile 128x128, 256 thr (8 warps, warp tile 32x64), K-chunk 64, cp.async 2-stage.
// B fragments loaded via ldmatrix.x4 (2 n-tiles per LDSM).
// ---------------------------------------------------------------------------
#define G1_LD 72
#define G1_TILE_B (128 * G1_LD * 2)      // 18432
#define G1_STAGE_B (2 * G1_TILE_B)      // 36864
#define G1_SMEM (2 * G1_STAGE_B)        // 73728

__global__ __launch_bounds__(256) void k_gemm1(const float* __restrict__ bias) {
    extern __shared__ char sm[];
    const int tid = threadIdx.x;
    const int w = tid >> 5;
    const int lane = tid & 31;
    const int wr = w >> 1;          // 0..3 : rows wr*32
    const int wc = w & 1;           // 0..1 : cols wc*64
    const int g = lane >> 2;
    const int t4 = lane & 3;
    const int m0 = blockIdx.x * 128;
    const int n0 = blockIdx.y * 128;

    float acc[2][8][4];
#pragma unroll
    for (int a = 0; a < 2; a++)
#pragma unroll
        for (int nt = 0; nt < 8; nt++)
#pragma unroll
            for (int e = 0; e < 4; e++) acc[a][nt][e] = 0.f;

    auto issue = [&](int kc, int st) {
        char* base = sm + st * G1_STAGE_B;
        uint32_t sa = smem_u32(base);
        uint32_t sb = smem_u32(base + G1_TILE_B);
#pragma unroll
        for (int it = 0; it < 4; it++) {
            int idx = tid + it * 256;          // 0..1023
            int r = idx >> 3, cu = idx & 7;
            cp_async16(sa + (r * G1_LD + cu * 8) * 2,
                       g_cbf + (size_t)(m0 + r) * DD + kc * 64 + cu * 8);
        }
#pragma unroll
        for (int it = 0; it < 4; it++) {
            int idx = tid + it * 256;
            int r = idx >> 3, cu = idx & 7;
            cp_async16(sb + (r * G1_LD + cu * 8) * 2,
                       g_Wt + (size_t)(n0 + r) * DD + kc * 64 + cu * 8);
        }
        cp_commit();
    };

    issue(0, 0);

    for (int kc = 0; kc < 8; kc++) {
        if (kc < 7) issue(kc + 1, (kc + 1) & 1);
        if (kc < 7) cp_wait<1>(); else cp_wait<0>();
        __syncthreads();
        char* base = sm + (kc & 1) * G1_STAGE_B;
        uint32_t sa = smem_u32(base);
        uint32_t sb = smem_u32(base + G1_TILE_B);
#pragma unroll
        for (int ks = 0; ks < 4; ks++) {
            uint32_t af[2][4];
#pragma unroll
            for (int a = 0; a < 2; a++) {
                uint32_t addr = sa + ((wr * 32 + a * 16 + (lane & 15)) * G1_LD +
                                      ks * 16 + (lane >> 4) * 8) * 2;
                ldm_x4(af[a][0], af[a][1], af[a][2], af[a][3], addr);
            }
#pragma unroll
            for (int np = 0; np < 4; np++) {
                uint32_t b0, b1, b2, b3;
                uint32_t addr = sb + ((wc * 64 + np * 16 + ((lane >> 4) & 1) * 8 +
                                       (lane & 7)) * G1_LD +
                                      ks * 16 + ((lane >> 3) & 1) * 8) * 2;
                ldm_x4(b0, b1, b2, b3, addr);
#pragma unroll
                for (int a = 0; a < 2; a++) {
                    mma_bf16(acc[a][2 * np], af[a][0], af[a][1], af[a][2], af[a][3], b0, b1);
                    mma_bf16(acc[a][2 * np + 1], af[a][0], af[a][1], af[a][2], af[a][3], b2, b3);
                }
            }
        }
        __syncthreads();
    }

    // Epilogue: bias + bf16 store
#pragma unroll
    for (int a = 0; a < 2; a++) {
        int r0 = m0 + wr * 32 + a * 16 + g;
#pragma unroll
        for (int nt = 0; nt < 8; nt++) {
            int col = n0 + wc * 64 + nt * 8 + t4 * 2;
            float bv0 = bias[col], bv1 = bias[col + 1];
            *(__nv_bfloat162*)(g_cproj + (size_t)r0 * DD + col) =
                __floats2bfloat162_rn(acc[a][nt][0] + bv0, acc[a][nt][1] + bv1);
            *(__nv_bfloat162*)(g_cproj + (size_t)(r0 + 8) * DD + col) =
                __floats2bfloat162_rn(acc[a][nt][2] + bv0, acc[a][nt][3] + bv1);
        }
    }
}

// ---------------------------------------------------------------------------
// Fused scores + LSE - diag.  Grid (98, 3): CTA = (t, 10 ks). 256 thr, 8 warps.
// C_t resident in SMEM (64x512). 3 phases of {4,4,2} ks; 2 warps per k,
// warp tile 32 rows x 64 cols. Z streamed in 128-col D-chunks, cp.async
// double-buffered (2 stages x 4 k-slots). B frags via ldmatrix.x4.
// ---------------------------------------------------------------------------
#define SC_LD 520
#define SC_BYTES (64 * SC_LD * 2)        // 66560
#define SZ_LD 136
#define SZ_SLOT (64 * SZ_LD * 2)         // 17408
#define SZ_BYTES (8 * SZ_SLOT)           // 139264
#define S_SMEM (SC_BYTES + SZ_BYTES + 64)  // 205888

__global__ __launch_bounds__(256) void k_scores() {
    extern __shared__ char sm[];
    __nv_bfloat16* sCp = (__nv_bfloat16*)sm;
    uint32_t sC = smem_u32(sCp);
    uint32_t sZ0 = sC + SC_BYTES;
    float* sRed = (float*)(sm + SC_BYTES + SZ_BYTES);

    const int t = blockIdx.x;
    const int kb10 = blockIdx.y * 10;
    const int tid = threadIdx.x;
    const int w = tid >> 5;
    const int lane = tid & 31;
    const int wk = w >> 1;          // k slot within phase (0..3)
    const int rh = w & 1;           // row half: rows rh*32..+32
    const int g = lane >> 2;
    const int t4 = lane & 3;

    // --- Prologue: C tile (group 0) + Z stages 0,1 (groups 1,2) ---
#pragma unroll
    for (int it = 0; it < 16; it++) {
        int idx = tid + it * 256;           // 0..4095 -> 64 rows x 64 uint4
        int r = idx >> 6, cu = idx & 63;
        cp_async16(sC + (r * SC_LD + cu * 8) * 2,
                   g_cproj + ((size_t)r * TT + t) * DD + cu * 8);
    }
    cp_commit();

    auto issue_z = [&](int it) {
        int p = it >> 2, ch = it & 3, st = it & 1;
        int kcnt = (p < 2) ? 4 : 2;
        for (int slot = 0; slot < kcnt; slot++) {
            int s = t + kb10 + p * 4 + slot + 1;
            uint32_t dst = sZ0 + (st * 4 + slot) * SZ_SLOT;
#pragma unroll
            for (int j = 0; j < 4; j++) {
                int idx = tid + j * 256;    // 0..1023 -> 64 rows x 16 uint4
                int r = idx >> 4, cu = idx & 15;
                cp_async16(dst + (r * SZ_LD + cu * 8) * 2,
                           g_zbf + ((size_t)r * TT + s) * DD + ch * 128 + cu * 8);
            }
        }
        cp_commit();
    };

    issue_z(0);
    issue_z(1);
    cp_wait<1>();       // C + stage0 ready
    __syncthreads();

    float acc[2][8][4];
#pragma unroll
    for (int a = 0; a < 2; a++)
#pragma unroll
        for (int nt = 0; nt < 8; nt++)
#pragma unroll
            for (int e = 0; e < 4; e++) acc[a][nt][e] = 0.f;

    for (int it = 0; it < 12; it++) {
        const int p = it >> 2, ch = it & 3;
        const int kcnt = (p < 2) ? 4 : 2;
        const bool active = (wk < kcnt);

        // --- Compute this chunk ---
        if (active) {
            uint32_t sz = sZ0 + ((it & 1) * 4 + wk) * SZ_SLOT;
#pragma unroll
            for (int ks = 0; ks < 8; ks++) {
                uint32_t af[2][4];
#pragma unroll
                for (int a = 0; a < 2; a++) {
                    uint32_t addr = sC + ((rh * 32 + a * 16 + (lane & 15)) * SC_LD +
                                          ch * 128 + ks * 16 + (lane >> 4) * 8) * 2;
                    ldm_x4(af[a][0], af[a][1], af[a][2], af[a][3], addr);
                }
#pragma unroll
                for (int np = 0; np < 4; np++) {
                    uint32_t b0, b1, b2, b3;
                    uint32_t addr = sz + ((np * 16 + ((lane >> 4) & 1) * 8 +
                                           (lane & 7)) * SZ_LD +
                                          ks * 16 + ((lane >> 3) & 1) * 8) * 2;
                    ldm_x4(b0, b1, b2, b3, addr);
#pragma unroll
                    for (int a = 0; a < 2; a++) {
                        mma_bf16(acc[a][2 * np], af[a][0], af[a][1], af[a][2], af[a][3], b0, b1);
                        mma_bf16(acc[a][2 * np + 1], af[a][0], af[a][1], af[a][2], af[a][3], b2, b3);
                    }
                }
            }
        }
        __syncthreads();                    // stage consumed by all warps

        if (it < 10) issue_z(it + 2);       // refill the just-consumed stage

        // --- End of phase: LSE - diag epilogue (overlaps in-flight cp.async) ---
        if (ch == 3) {
            float local = 0.f;
            if (active) {
#pragma unroll
                for (int a = 0; a < 2; a++) {
#pragma unroll
                    for (int rp = 0; rp < 2; rp++) {
                        const int e0 = rp * 2;
                        float m = -3.4e38f;
#pragma unroll
                        for (int nt = 0; nt < 8; nt++)
                            m = fmaxf(m, fmaxf(acc[a][nt][e0], acc[a][nt][e0 + 1]));
                        m = fmaxf(m, __shfl_xor_sync(0xffffffffu, m, 1));
                        m = fmaxf(m, __shfl_xor_sync(0xffffffffu, m, 2));
                        float se = 0.f;
#pragma unroll
                        for (int nt = 0; nt < 8; nt++) {
                            se += expf((acc[a][nt][e0] - m) * INV_TEMP);
                            se += expf((acc[a][nt][e0 + 1] - m) * INV_TEMP);
                        }
                        se += __shfl_xor_sync(0xffffffffu, se, 1);
                        se += __shfl_xor_sync(0xffffffffu, se, 2);
                        float lse = m * INV_TEMP + logf(se);
                        int i = rh * 32 + a * 16 + rp * 8 + g;   // row == diag col
                        if (t4 == ((i >> 1) & 3))
                            local += lse - acc[a][i >> 3][e0 + (i & 1)] * INV_TEMP;
                    }
                }
            }
#pragma unroll
            for (int off = 16; off > 0; off >>= 1)
                local += __shfl_xor_sync(0xffffffffu, local, off);
            if (lane == 0) sRed[w] = local;
            __syncthreads();
            if (tid < kcnt)
                g_partials[t * HH + kb10 + p * 4 + tid] = sRed[2 * tid] + sRed[2 * tid + 1];

            // zero accumulators for next phase
#pragma unroll
            for (int a = 0; a < 2; a++)
#pragma unroll
                for (int nt = 0; nt < 8; nt++)
#pragma unroll
                    for (int e = 0; e < 4; e++) acc[a][nt][e] = 0.f;
        }

        if (it < 11) {
            if (it < 10) cp_wait<1>(); else cp_wait<0>();
            __syncthreads();                // next stage ready for all warps
        }
    }
}

// ---------------------------------------------------------------------------
// Final deterministic reduction
// ---------------------------------------------------------------------------
__global__ void k_reduce(float* __restrict__ out) {
    __shared__ float sh[256];
    int tid = threadIdx.x;
    float ssum = 0.f;
    for (int i = tid; i < TM * HH; i += 256) ssum += g_partials[i];
    sh[tid] = ssum;
    __syncthreads();
    for (int off = 128; off > 0; off >>= 1) {
        if (tid < off) sh[tid] += sh[tid + off];
        __syncthreads();
    }
    if (tid == 0) out[0] = sh[0] / (float)(TM * HH * BB);
}

// ---------------------------------------------------------------------------
extern "C" void kernel_launch(void* const* d_in, const int* in_sizes, int n_in,
                              void* d_out, int out_size) {
    const float* z = (const float*)d_in[0];
    const float* c = (const float*)d_in[1];
    const float* W = (const float*)d_in[2];
    const float* bias = (const float*)d_in[3];
    float* out = (float*)d_out;
    (void)in_sizes; (void)n_in; (void)out_size;

    cudaFuncSetAttribute(k_scores, cudaFuncAttributeMaxDynamicSharedMemorySize, S_SMEM);
    cudaFuncSetAttribute(k_gemm1, cudaFuncAttributeMaxDynamicSharedMemorySize, G1_SMEM);

    __nv_bfloat16* zb = nullptr;
    __nv_bfloat16* cb = nullptr;
    cudaGetSymbolAddress((void**)&zb, g_zbf);
    cudaGetSymbolAddress((void**)&cb, g_cbf);

    k_convert<<<4096, 256>>>(z, zb);
    k_convert<<<4096, 256>>>(c, cb);
    k_convert_w<<<(DD * DD + 511) / 512, 512>>>(W);
    k_gemm1<<<dim3(64, 4), 256, G1_SMEM>>>(bias);
    k_scores<<<dim3(TM, 3), 256, S_SMEM>>>();
    k_reduce<<<1, 256>>>(out);
}

// round 6
// speedup vs baseline: 2.3707x; 1.0364x over previous
#include <cuda_runtime.h>
#include <cuda_bf16.h>
#include <cstdint>

// Problem constants
#define BB 64
#define TT 128
#define DD 512
#define HH 30
#define TM 98
static constexpr float INV_TEMP = 1.0f / 0.07f;

// Scratch (device globals: no allocation allowed)
__device__ __align__(16) __nv_bfloat16 g_zbf[BB * TT * DD];    // bf16 z_seq
__device__ __align__(16) __nv_bfloat16 g_cbf[BB * TT * DD];    // bf16 c_seq
__device__ __align__(16) __nv_bfloat16 g_cproj[BB * TT * DD];  // bf16 c_proj
__device__ __align__(16) __nv_bfloat16 g_Wt[DD * DD];          // bf16 W^T ([n][p])
__device__ float g_partials[TM * HH];

// ---------------------------------------------------------------------------
// PTX helpers
// ---------------------------------------------------------------------------
__device__ __forceinline__ uint32_t smem_u32(const void* p) {
    return (uint32_t)__cvta_generic_to_shared(p);
}
__device__ __forceinline__ void ldm_x4(uint32_t& a0, uint32_t& a1, uint32_t& a2,
                                       uint32_t& a3, uint32_t addr) {
    asm volatile("ldmatrix.sync.aligned.m8n8.x4.shared.b16 {%0,%1,%2,%3}, [%4];\n"
                 : "=r"(a0), "=r"(a1), "=r"(a2), "=r"(a3) : "r"(addr));
}
__device__ __forceinline__ void mma_bf16(float* c, uint32_t a0, uint32_t a1,
                                         uint32_t a2, uint32_t a3,
                                         uint32_t b0, uint32_t b1) {
    asm volatile(
        "mma.sync.aligned.m16n8k16.row.col.f32.bf16.bf16.f32 "
        "{%0,%1,%2,%3}, {%4,%5,%6,%7}, {%8,%9}, {%0,%1,%2,%3};\n"
        : "+f"(c[0]), "+f"(c[1]), "+f"(c[2]), "+f"(c[3])
        : "r"(a0), "r"(a1), "r"(a2), "r"(a3), "r"(b0), "r"(b1));
}
__device__ __forceinline__ void cp_async16(uint32_t dst, const void* src) {
    asm volatile("cp.async.ca.shared.global [%0], [%1], 16;\n" :: "r"(dst), "l"(src));
}
__device__ __forceinline__ void cp_commit() {
    asm volatile("cp.async.commit_group;\n");
}
template <int N>
__device__ __forceinline__ void cp_wait() {
    asm volatile("cp.async.wait_group %0;\n" :: "n"(N));
}

// ---------------------------------------------------------------------------
// Convert fp32 -> bf16 (vectorized)
// ---------------------------------------------------------------------------
__global__ void k_convert(const float* __restrict__ src, __nv_bfloat16* __restrict__ dst) {
    int i = blockIdx.x * blockDim.x + threadIdx.x;
    int idx = i * 4;
    if (idx < BB * TT * DD) {
        float4 v = *(const float4*)(src + idx);
        *(__nv_bfloat162*)(dst + idx) = __floats2bfloat162_rn(v.x, v.y);
        *(__nv_bfloat162*)(dst + idx + 2) = __floats2bfloat162_rn(v.z, v.w);
    }
}

// Transpose+convert W fp32 [p][n] -> bf16 g_Wt [n][p]
__global__ void k_convert_w(const float* __restrict__ W) {
    int i = blockIdx.x * blockDim.x + threadIdx.x;
    if (i < DD * DD) {
        int n = i >> 9;
        int p = i & 511;
        g_Wt[i] = __float2bfloat16(W[p * DD + n]);
    }
}

// ---------------------------------------------------------------------------
// GEMM1: c_proj = c @ W + b.  M=8192, N=512, K=512. (unchanged from R5)
// ---------------------------------------------------------------------------
#define G1_LD 72
#define G1_TILE_B (128 * G1_LD * 2)      // 18432
#define G1_STAGE_B (2 * G1_TILE_B)      // 36864
#define G1_SMEM (2 * G1_STAGE_B)        // 73728

__global__ __launch_bounds__(256) void k_gemm1(const float* __restrict__ bias) {
    extern __shared__ char sm[];
    const int tid = threadIdx.x;
    const int w = tid >> 5;
    const int lane = tid & 31;
    const int wr = w >> 1;
    const int wc = w & 1;
    const int g = lane >> 2;
    const int t4 = lane & 3;
    const int m0 = blockIdx.x * 128;
    const int n0 = blockIdx.y * 128;

    float acc[2][8][4];
#pragma unroll
    for (int a = 0; a < 2; a++)
#pragma unroll
        for (int nt = 0; nt < 8; nt++)
#pragma unroll
            for (int e = 0; e < 4; e++) acc[a][nt][e] = 0.f;

    auto issue = [&](int kc, int st) {
        char* base = sm + st * G1_STAGE_B;
        uint32_t sa = smem_u32(base);
        uint32_t sb = smem_u32(base + G1_TILE_B);
#pragma unroll
        for (int it = 0; it < 4; it++) {
            int idx = tid + it * 256;
            int r = idx >> 3, cu = idx & 7;
            cp_async16(sa + (r * G1_LD + cu * 8) * 2,
                       g_cbf + (size_t)(m0 + r) * DD + kc * 64 + cu * 8);
        }
#pragma unroll
        for (int it = 0; it < 4; it++) {
            int idx = tid + it * 256;
            int r = idx >> 3, cu = idx & 7;
            cp_async16(sb + (r * G1_LD + cu * 8) * 2,
                       g_Wt + (size_t)(n0 + r) * DD + kc * 64 + cu * 8);
        }
        cp_commit();
    };

    issue(0, 0);

    for (int kc = 0; kc < 8; kc++) {
        if (kc < 7) issue(kc + 1, (kc + 1) & 1);
        if (kc < 7) cp_wait<1>(); else cp_wait<0>();
        __syncthreads();
        char* base = sm + (kc & 1) * G1_STAGE_B;
        uint32_t sa = smem_u32(base);
        uint32_t sb = smem_u32(base + G1_TILE_B);
#pragma unroll
        for (int ks = 0; ks < 4; ks++) {
            uint32_t af[2][4];
#pragma unroll
            for (int a = 0; a < 2; a++) {
                uint32_t addr = sa + ((wr * 32 + a * 16 + (lane & 15)) * G1_LD +
                                      ks * 16 + (lane >> 4) * 8) * 2;
                ldm_x4(af[a][0], af[a][1], af[a][2], af[a][3], addr);
            }
#pragma unroll
            for (int np = 0; np < 4; np++) {
                uint32_t b0, b1, b2, b3;
                uint32_t addr = sb + ((wc * 64 + np * 16 + ((lane >> 4) & 1) * 8 +
                                       (lane & 7)) * G1_LD +
                                      ks * 16 + ((lane >> 3) & 1) * 8) * 2;
                ldm_x4(b0, b1, b2, b3, addr);
#pragma unroll
                for (int a = 0; a < 2; a++) {
                    mma_bf16(acc[a][2 * np], af[a][0], af[a][1], af[a][2], af[a][3], b0, b1);
                    mma_bf16(acc[a][2 * np + 1], af[a][0], af[a][1], af[a][2], af[a][3], b2, b3);
                }
            }
        }
        __syncthreads();
    }

#pragma unroll
    for (int a = 0; a < 2; a++) {
        int r0 = m0 + wr * 32 + a * 16 + g;
#pragma unroll
        for (int nt = 0; nt < 8; nt++) {
            int col = n0 + wc * 64 + nt * 8 + t4 * 2;
            float bv0 = bias[col], bv1 = bias[col + 1];
            *(__nv_bfloat162*)(g_cproj + (size_t)r0 * DD + col) =
                __floats2bfloat162_rn(acc[a][nt][0] + bv0, acc[a][nt][1] + bv1);
            *(__nv_bfloat162*)(g_cproj + (size_t)(r0 + 8) * DD + col) =
                __floats2bfloat162_rn(acc[a][nt][2] + bv0, acc[a][nt][3] + bv1);
        }
    }
}

// ---------------------------------------------------------------------------
// Fused scores + LSE - diag, diagonal-block version.
// Grid (49, 3): CTA = (t-pair {t0,t0+1}, s-window). 256 thr, 8 warps.
// C for BOTH t's resident in SMEM as M=128 (rows 0-63: t0, 64-127: t0+1).
// s-window: y=0 -> s in [t0+1, t0+11] (11), y=1 -> [t0+12, t0+21] (10),
//           y=2 -> [t0+22, t0+31] (10).  Each Z_s tile serves 2 (t,k) pairs.
// Phase = 2 s-slots (4 warps each, warp tile 32x64). Z double-buffered
// (2 stages x 2 slots) over 4 D-chunks of 128. Epilogue masks k outside [1,30].
// ---------------------------------------------------------------------------
#define SC_LD 520
#define SC_BYTES (128 * SC_LD * 2)       // 133120
#define SZ_LD 136
#define SZ_SLOT (64 * SZ_LD * 2)         // 17408
#define SZ_BYTES (4 * SZ_SLOT)           // 69632
#define S_SMEM (SC_BYTES + SZ_BYTES + 64)  // 202816

__global__ __launch_bounds__(256) void k_scores() {
    extern __shared__ char sm[];
    uint32_t sC = smem_u32(sm);
    uint32_t sZ0 = sC + SC_BYTES;
    float* sRed = (float*)(sm + SC_BYTES + SZ_BYTES);

    const int t0 = blockIdx.x * 2;
    const int y = blockIdx.y;
    const int s_base = t0 + 1 + ((y == 0) ? 0 : (y == 1) ? 11 : 21);
    const int win = (y == 0) ? 11 : 10;
    const int P = (win + 1) >> 1;       // phases (2 s per phase; last may be 1)
    const int ITERS = 4 * P;

    const int tid = threadIdx.x;
    const int w = tid >> 5;
    const int lane = tid & 31;
    const int slot = w >> 2;            // s-slot within phase (0/1)
    const int wr = w & 3;               // row quarter: rows wr*32..+32 of M=128
    const int g = lane >> 2;
    const int t4 = lane & 3;

    // --- Prologue: C tiles for t0 and t0+1 (rows 0-63 / 64-127) ---
#pragma unroll
    for (int it = 0; it < 32; it++) {
        int idx = tid + it * 256;           // 0..8191 -> 128 rows x 64 uint4
        int r = idx >> 6, cu = idx & 63;
        int i = r & 63, tt = t0 + (r >> 6);
        cp_async16(sC + (r * SC_LD + cu * 8) * 2,
                   g_cproj + ((size_t)i * TT + tt) * DD + cu * 8);
    }
    cp_commit();

    auto issue_z = [&](int it) {
        int p = it >> 2, ch = it & 3, st = it & 1;
#pragma unroll
        for (int sl = 0; sl < 2; sl++) {
            if (2 * p + sl >= win) break;
            int s = s_base + 2 * p + sl;
            uint32_t dst = sZ0 + (st * 2 + sl) * SZ_SLOT;
#pragma unroll
            for (int j = 0; j < 4; j++) {
                int idx = tid + j * 256;    // 0..1023 -> 64 rows x 16 uint4
                int r = idx >> 4, cu = idx & 15;
                cp_async16(dst + (r * SZ_LD + cu * 8) * 2,
                           g_zbf + ((size_t)r * TT + s) * DD + ch * 128 + cu * 8);
            }
        }
        cp_commit();
    };

    issue_z(0);
    issue_z(1);
    cp_wait<1>();       // C + stage0 ready
    __syncthreads();

    float acc[2][8][4];
#pragma unroll
    for (int a = 0; a < 2; a++)
#pragma unroll
        for (int nt = 0; nt < 8; nt++)
#pragma unroll
            for (int e = 0; e < 4; e++) acc[a][nt][e] = 0.f;

    for (int it = 0; it < ITERS; it++) {
        const int p = it >> 2, ch = it & 3;
        const bool slot_active = (2 * p + slot) < win;

        // --- Compute this D-chunk ---
        if (slot_active) {
            uint32_t sz = sZ0 + ((it & 1) * 2 + slot) * SZ_SLOT;
#pragma unroll
            for (int ks = 0; ks < 8; ks++) {
                uint32_t af[2][4];
#pragma unroll
                for (int a = 0; a < 2; a++) {
                    uint32_t addr = sC + ((wr * 32 + a * 16 + (lane & 15)) * SC_LD +
                                          ch * 128 + ks * 16 + (lane >> 4) * 8) * 2;
                    ldm_x4(af[a][0], af[a][1], af[a][2], af[a][3], addr);
                }
#pragma unroll
                for (int np = 0; np < 4; np++) {
                    uint32_t b0, b1, b2, b3;
                    uint32_t addr = sz + ((np * 16 + ((lane >> 4) & 1) * 8 +
                                           (lane & 7)) * SZ_LD +
                                          ks * 16 + ((lane >> 3) & 1) * 8) * 2;
                    ldm_x4(b0, b1, b2, b3, addr);
#pragma unroll
                    for (int a = 0; a < 2; a++) {
                        mma_bf16(acc[a][2 * np], af[a][0], af[a][1], af[a][2], af[a][3], b0, b1);
                        mma_bf16(acc[a][2 * np + 1], af[a][0], af[a][1], af[a][2], af[a][3], b2, b3);
                    }
                }
            }
        }
        __syncthreads();                    // stage fully consumed

        if (it + 2 < ITERS) issue_z(it + 2);

        // --- End of phase: LSE - diag epilogue ---
        if (ch == 3) {
            const int s = s_base + 2 * p + slot;
            const int th = wr >> 1;         // row half: 0 -> t0, 1 -> t0+1
            const int tcur = t0 + th;
            const int k = s - tcur;
            const bool valid = slot_active && (k >= 1) && (k <= 30);

            float local = 0.f;
            if (valid) {
#pragma unroll
                for (int a = 0; a < 2; a++) {
#pragma unroll
                    for (int rp = 0; rp < 2; rp++) {
                        const int e0 = rp * 2;
                        float m = -3.4e38f;
#pragma unroll
                        for (int nt = 0; nt < 8; nt++)
                            m = fmaxf(m, fmaxf(acc[a][nt][e0], acc[a][nt][e0 + 1]));
                        m = fmaxf(m, __shfl_xor_sync(0xffffffffu, m, 1));
                        m = fmaxf(m, __shfl_xor_sync(0xffffffffu, m, 2));
                        float se = 0.f;
#pragma unroll
                        for (int nt = 0; nt < 8; nt++) {
                            se += expf((acc[a][nt][e0] - m) * INV_TEMP);
                            se += expf((acc[a][nt][e0 + 1] - m) * INV_TEMP);
                        }
                        se += __shfl_xor_sync(0xffffffffu, se, 1);
                        se += __shfl_xor_sync(0xffffffffu, se, 2);
                        float lse = m * INV_TEMP + logf(se);
                        int r = wr * 32 + a * 16 + rp * 8 + g;   // 0..127
                        int j = r & 63;                          // diag col
                        if (t4 == ((j >> 1) & 3))
                            local += lse - acc[a][j >> 3][e0 + (j & 1)] * INV_TEMP;
                    }
                }
            }
#pragma unroll
            for (int off = 16; off > 0; off >>= 1)
                local += __shfl_xor_sync(0xffffffffu, local, off);
            if (lane == 0) sRed[w] = local;
            __syncthreads();
            // sRed[w]: w = slot*4 + half*2 + {0,1}
            if (tid < 4) {
                int wsl = tid >> 1, half = tid & 1;
                if (2 * p + wsl < win) {
                    int ss = s_base + 2 * p + wsl;
                    int tt = t0 + half;
                    int kk = ss - tt;
                    if (kk >= 1 && kk <= 30)
                        g_partials[tt * HH + kk - 1] =
                            sRed[wsl * 4 + half * 2] + sRed[wsl * 4 + half * 2 + 1];
                }
            }
            // zero accumulators for next phase
#pragma unroll
            for (int a = 0; a < 2; a++)
#pragma unroll
                for (int nt = 0; nt < 8; nt++)
#pragma unroll
                    for (int e = 0; e < 4; e++) acc[a][nt][e] = 0.f;
        }

        if (it + 1 < ITERS) {
            if (it + 2 < ITERS) cp_wait<1>(); else cp_wait<0>();
            __syncthreads();                // next stage ready
        }
    }
}

// ---------------------------------------------------------------------------
// Final deterministic reduction
// ---------------------------------------------------------------------------
__global__ void k_reduce(float* __restrict__ out) {
    __shared__ float sh[256];
    int tid = threadIdx.x;
    float ssum = 0.f;
    for (int i = tid; i < TM * HH; i += 256) ssum += g_partials[i];
    sh[tid] = ssum;
    __syncthreads();
    for (int off = 128; off > 0; off >>= 1) {
        if (tid < off) sh[tid] += sh[tid + off];
        __syncthreads();
    }
    if (tid == 0) out[0] = sh[0] / (float)(TM * HH * BB);
}

// ---------------------------------------------------------------------------
extern "C" void kernel_launch(void* const* d_in, const int* in_sizes, int n_in,
                              void* d_out, int out_size) {
    const float* z = (const float*)d_in[0];
    const float* c = (const float*)d_in[1];
    const float* W = (const float*)d_in[2];
    const float* bias = (const float*)d_in[3];
    float* out = (float*)d_out;
    (void)in_sizes; (void)n_in; (void)out_size;

    cudaFuncSetAttribute(k_scores, cudaFuncAttributeMaxDynamicSharedMemorySize, S_SMEM);
    cudaFuncSetAttribute(k_gemm1, cudaFuncAttributeMaxDynamicSharedMemorySize, G1_SMEM);

    __nv_bfloat16* zb = nullptr;
    __nv_bfloat16* cb = nullptr;
    cudaGetSymbolAddress((void**)&zb, g_zbf);
    cudaGetSymbolAddress((void**)&cb, g_cbf);

    k_convert<<<4096, 256>>>(z, zb);
    k_convert<<<4096, 256>>>(c, cb);
    k_convert_w<<<(DD * DD + 511) / 512, 512>>>(W);
    k_gemm1<<<dim3(64, 4), 256, G1_SMEM>>>(bias);
    k_scores<<<dim3(49, 3), 256, S_SMEM>>>();
    k_reduce<<<1, 256>>>(out);
}